// round 8
// baseline (speedup 1.0000x reference)
#include <cuda_runtime.h>
#include <cstdint>

#define BATCH 32
#define H0 260
#define W0 1004
#define H1 258
#define W1W 1002
#define H1P 1004
#define H2 256
#define W2W 1000
#define D1 27
#define D2 45

__device__ float g_h1[(size_t)BATCH * 5 * H1 * H1P];
__device__ float g_rsp[(size_t)BATCH * 5 * H1 * 2];
__device__ float g_re[(size_t)BATCH * 5 * H1 * 4];
__device__ float g_xrs[(size_t)BATCH * 3 * H0 * 3];
__device__ float g_pd[(size_t)BATCH * 5 * H2 * 2 * 10];
__device__ int   g_fh1[5];
__device__ int   g_fh2[5];
__device__ int   g_m1[BATCH * 5];
__device__ int   g_m2[BATCH * 5];

// ---------------- filter hashes ---------------------------------------------
__global__ void k_filter_hash(const float* __restrict__ W1, const float* __restrict__ W2,
                              const float* __restrict__ a1, const float* __restrict__ b1,
                              const float* __restrict__ a2, const float* __restrict__ b2) {
    int t = threadIdx.x, lane = t & 31, wrp = t >> 5;
    const float* W = wrp ? W2 : W1;
    const float* a = wrp ? a2 : a1;
    float bb = wrp ? *b2 : *b1;
    int d = wrp ? D2 : D1;
    float ss = 0.f;
    if (lane < 5) for (int k = 0; k < d; ++k) { float v = W[lane * d + k]; ss += v * v; }
    float nrm = sqrtf(ss);
    for (int o = 16; o; o >>= 1) nrm = fmaxf(nrm, __shfl_xor_sync(0xffffffffu, nrm, o));
    float scale = 0.99f / nrm;
    if (lane < 5) {
        float dot = 0.f;
        for (int k = 0; k < d; ++k) dot += (W[lane * d + k] * scale) * a[k];
        float n2 = ss * scale * scale;
        float p2 = n2 * n2, p4 = p2 * p2, p8 = p4 * p4, p16 = p8 * p8;
        dot += n2 * a[d] + p2 * a[d + 1] + p4 * a[d + 2] + p8 * a[d + 3] + p16 * a[d + 4] + bb;
        int h = (int)floorf(dot / 0.1f);
        (wrp ? g_fh2 : g_fh1)[lane] = h & 1;
    }
}

// ---------------- x row restricted sums -------------------------------------
__global__ __launch_bounds__(256) void k_xrows(const float* __restrict__ x) {
    int blk = blockIdx.x, bc = blk >> 2, q = blk & 3;
    int r0 = q * 65;
    int tid = threadIdx.x, lane = tid & 31, wrp = tid >> 5;
    for (int r = r0 + wrp; r < r0 + 65; r += 8) {
        const float* row = x + ((size_t)bc * H0 + r) * W0;
        float s = 0.f;
        for (int col = lane; col < W0; col += 32) s += row[col];
        for (int o = 16; o; o >>= 1) s += __shfl_down_sync(0xffffffffu, s, o);
        if (lane == 0) {
            float e0 = row[0], e1 = row[1], ea = row[W0 - 2], eb = row[W0 - 1];
            float* outp = g_xrs + ((size_t)bc * H0 + r) * 3;
            outp[0] = s - ea - eb;
            outp[1] = s - e0 - eb;
            outp[2] = s - e0 - e1;
        }
    }
}

// ---------------- layer-1 query hash + mask ---------------------------------
__global__ void k_q1mask(const float* __restrict__ a, const float* __restrict__ bp) {
    __shared__ float q[D1];
    int b = blockIdx.x, t = threadIdx.x;
    if (t < D1) {
        int c = t / 9, rem = t % 9, i = rem / 3, j = rem % 3;
        const float* base = g_xrs + ((size_t)(b * 3 + c) * H0) * 3;
        double s = 0.0;
        for (int r = i; r < i + 258; ++r) s += (double)base[r * 3 + j];
        q[t] = (float)(s / (258.0 * 1002.0));
    }
    __syncthreads();
    if (t == 0) {
        float ss = 0.f;
        for (int k = 0; k < D1; ++k) ss += q[k] * q[k];
        float inv = 1.0f / fmaxf(sqrtf(ss), 1e-12f);
        double dot = 0.0;
        for (int k = 0; k < D1; ++k) dot += (double)(q[k] * inv) * (double)a[k];
        dot += 0.5 * ((double)a[D1] + a[D1 + 1] + a[D1 + 2] + a[D1 + 3] + a[D1 + 4]) + (double)*bp;
        int qh = ((int)floor(dot / 0.1)) & 1;
        for (int c = 0; c < 5; ++c) g_m1[b * 5 + c] = (g_fh1[c] == qh) ? 1 : 0;
    }
}

// ---------------- conv1: 4 rows x half-width, 2 channels per pass ----------
#define C1_SMEM (3 * 6 * 512 * 4)

__global__ __launch_bounds__(128, 5) void k_conv1(const float* __restrict__ x,
                                                  const float* __restrict__ W1) {
    extern __shared__ float xs[];            // [3][6][512]
    __shared__ float s_warp[4][4][2];
    __shared__ float sE[4][2][2];
    __shared__ int cl1[5], s_na;
    int bid = blockIdx.x;
    int b = bid / 130, rem2 = bid % 130;
    int g = rem2 >> 1, half = rem2 & 1;
    int i0 = g * 4, base = half * 500;
    int tid = threadIdx.x, lane = tid & 31, wrp = tid >> 5;

    if (tid == 0) {
        int na = 0;
        for (int c = 0; c < 5; ++c) if (g_m1[b * 5 + c]) cl1[na++] = c;
        s_na = na;
    }
    for (int v = tid; v < 3 * 6 * 128; v += 128) {
        int cc = v / 768, rm = v % 768;
        int rr = rm >> 7, jj = rm & 127;
        int col = base + jj * 4;
        float4 val = make_float4(0.f, 0.f, 0.f, 0.f);
        if (col + 3 < W0 && i0 + rr < H0)
            val = *(const float4*)&x[((size_t)(b * 3 + cc) * H0 + (i0 + rr)) * W0 + col];
        ((float4*)xs)[v] = val;
    }
    __syncthreads();
    int na = s_na;
    bool tail = (half == 1 && tid == 125);
    bool valid = (tid < 125) || tail;
    int j0 = tid * 4;

    for (int p = 0; p < (na + 1) / 2; ++p) {
        int o0 = cl1[2 * p];
        int o1 = (2 * p + 1 < na) ? cl1[2 * p + 1] : -1;
        int o1w = (o1 >= 0) ? o1 : o0;
        float acc0[4][4], acc1[4][4];
#pragma unroll
        for (int ri = 0; ri < 4; ++ri)
#pragma unroll
            for (int k = 0; k < 4; ++k) { acc0[ri][k] = 0.f; acc1[ri][k] = 0.f; }
        if (valid) {
#pragma unroll
            for (int cc = 0; cc < 3; ++cc) {
                float w0r[9], w1r[9];
#pragma unroll
                for (int k = 0; k < 9; ++k) {
                    w0r[k] = __ldg(W1 + o0 * 27 + cc * 9 + k);
                    w1r[k] = __ldg(W1 + o1w * 27 + cc * 9 + k);
                }
#pragma unroll
                for (int rr = 0; rr < 6; ++rr) {
                    const float* ptr = &xs[(cc * 6 + rr) * 512 + j0];
                    float4 v4 = *(const float4*)ptr;
                    float2 v2 = *(const float2*)(ptr + 4);
#pragma unroll
                    for (int di = 0; di < 3; ++di) {
                        int ri = rr - di;
                        if (ri >= 0 && ri < 4) {
                            float a0 = w0r[di * 3 + 0], a1 = w0r[di * 3 + 1], a2 = w0r[di * 3 + 2];
                            acc0[ri][0] += v4.x * a0 + v4.y * a1 + v4.z * a2;
                            acc0[ri][1] += v4.y * a0 + v4.z * a1 + v4.w * a2;
                            acc0[ri][2] += v4.z * a0 + v4.w * a1 + v2.x * a2;
                            acc0[ri][3] += v4.w * a0 + v2.x * a1 + v2.y * a2;
                            float b0 = w1r[di * 3 + 0], b1 = w1r[di * 3 + 1], b2 = w1r[di * 3 + 2];
                            acc1[ri][0] += v4.x * b0 + v4.y * b1 + v4.z * b2;
                            acc1[ri][1] += v4.y * b0 + v4.z * b1 + v4.w * b2;
                            acc1[ri][2] += v4.z * b0 + v4.w * b1 + v2.x * b2;
                            acc1[ri][3] += v4.w * b0 + v2.x * b1 + v2.y * b2;
                        }
                    }
                }
            }
        }
#pragma unroll
        for (int ri = 0; ri < 4; ++ri) {
            bool rowok = (i0 + ri < H1);
            float p00 = fmaxf(acc0[ri][0], 0.f), p01 = fmaxf(acc0[ri][1], 0.f);
            float p02 = fmaxf(acc0[ri][2], 0.f), p03 = fmaxf(acc0[ri][3], 0.f);
            float p10 = fmaxf(acc1[ri][0], 0.f), p11 = fmaxf(acc1[ri][1], 0.f);
            float p12 = fmaxf(acc1[ri][2], 0.f), p13 = fmaxf(acc1[ri][3], 0.f);
            float part0 = 0.f, part1 = 0.f;
            if (valid && rowok) {
                size_t r0b = ((size_t)(b * 5 + o0) * H1 + (i0 + ri)) * H1P + base + j0;
                if (!tail) {
                    *(float4*)(g_h1 + r0b) = make_float4(p00, p01, p02, p03);
                    part0 = p00 + p01 + p02 + p03;
                } else {
                    g_h1[r0b + 0] = p00; g_h1[r0b + 1] = p01;
                    part0 = p00 + p01;
                }
                if (o1 >= 0) {
                    size_t r1b = ((size_t)(b * 5 + o1) * H1 + (i0 + ri)) * H1P + base + j0;
                    if (!tail) {
                        *(float4*)(g_h1 + r1b) = make_float4(p10, p11, p12, p13);
                        part1 = p10 + p11 + p12 + p13;
                    } else {
                        g_h1[r1b + 0] = p10; g_h1[r1b + 1] = p11;
                        part1 = p10 + p11;
                    }
                }
            }
            if ((half == 0 && tid == 0) || (half == 1 && tid == 125)) {
                sE[ri][0][0] = p00; sE[ri][1][0] = p01;
                sE[ri][0][1] = p10; sE[ri][1][1] = p11;
            }
            for (int o2 = 16; o2; o2 >>= 1) {
                part0 += __shfl_down_sync(0xffffffffu, part0, o2);
                part1 += __shfl_down_sync(0xffffffffu, part1, o2);
            }
            if (lane == 0) { s_warp[wrp][ri][0] = part0; s_warp[wrp][ri][1] = part1; }
        }
        __syncthreads();
        if (tid < 8) {
            int ch = tid >> 2, r = tid & 3;
            int oc = ch ? o1 : o0;
            if (oc >= 0 && i0 + r < H1) {
                float full = s_warp[0][r][ch] + s_warp[1][r][ch] +
                             s_warp[2][r][ch] + s_warp[3][r][ch];
                size_t row = (size_t)(b * 5 + oc) * H1 + (i0 + r);
                g_rsp[row * 2 + half] = full;
                g_re[row * 4 + half * 2 + 0] = sE[r][0][ch];
                g_re[row * 4 + half * 2 + 1] = sE[r][1][ch];
            }
        }
        __syncthreads();
    }
}

// ---------------- layer-2 query hash + mask ---------------------------------
__global__ void k_q2mask(const float* __restrict__ a, const float* __restrict__ bp) {
    __shared__ float q[D2];
    int b = blockIdx.x, tid = threadIdx.x, lane = tid & 31, c = tid >> 5;
    if (c < 5) {
        if (!g_m1[b * 5 + c]) {
            if (lane < 9) q[c * 9 + lane] = 0.f;
        } else {
            const float* P = g_rsp + (size_t)(b * 5 + c) * H1 * 2;
            const float* E = g_re + (size_t)(b * 5 + c) * H1 * 4;
            double F = 0.0, E0 = 0.0, E1 = 0.0, EA = 0.0, EB = 0.0;
            for (int r = lane; r < H1; r += 32) {
                F  += (double)P[r * 2 + 0] + (double)P[r * 2 + 1];
                E0 += (double)E[r * 4 + 0];
                E1 += (double)E[r * 4 + 1];
                EA += (double)E[r * 4 + 2];
                EB += (double)E[r * 4 + 3];
            }
            for (int o = 16; o; o >>= 1) {
                F  += __shfl_down_sync(0xffffffffu, F, o);
                E0 += __shfl_down_sync(0xffffffffu, E0, o);
                E1 += __shfl_down_sync(0xffffffffu, E1, o);
                EA += __shfl_down_sync(0xffffffffu, EA, o);
                EB += __shfl_down_sync(0xffffffffu, EB, o);
            }
            if (lane == 0) {
                double tot[3] = {F - EA - EB, F - E0 - EB, F - E0 - E1};
                const int rows[4] = {0, 1, 256, 257};
                double rsv[4][3];
                for (int k = 0; k < 4; ++k) {
                    int r = rows[k];
                    double fr = (double)P[r * 2 + 0] + (double)P[r * 2 + 1];
                    double e0 = E[r * 4 + 0], e1 = E[r * 4 + 1];
                    double ea = E[r * 4 + 2], eb = E[r * 4 + 3];
                    rsv[k][0] = fr - ea - eb;
                    rsv[k][1] = fr - e0 - eb;
                    rsv[k][2] = fr - e0 - e1;
                }
                const int exA[3] = {2, 0, 0};
                const int exB[3] = {3, 3, 1};
                for (int i = 0; i < 3; ++i)
                    for (int jo = 0; jo < 3; ++jo)
                        q[c * 9 + i * 3 + jo] =
                            (float)((tot[jo] - rsv[exA[i]][jo] - rsv[exB[i]][jo]) / 256000.0);
            }
        }
    }
    __syncthreads();
    if (tid == 0) {
        float ss = 0.f;
        for (int k = 0; k < D2; ++k) ss += q[k] * q[k];
        float inv = 1.0f / fmaxf(sqrtf(ss), 1e-12f);
        double dot = 0.0;
        for (int k = 0; k < D2; ++k) dot += (double)(q[k] * inv) * (double)a[k];
        dot += 0.5 * ((double)a[D2] + a[D2 + 1] + a[D2 + 2] + a[D2 + 3] + a[D2 + 4]) + (double)*bp;
        int qh = ((int)floor(dot / 0.1)) & 1;
        for (int cc = 0; cc < 5; ++cc) g_m2[b * 5 + cc] = (g_fh2[cc] == qh) ? 1 : 0;
    }
}

// ---------------- conv2 + relu + fused linear, 1 row/quad ------------------
#define C2_SMEM (5 * 6 * 512 * 4)

__global__ __launch_bounds__(512, 2) void k_conv2pd(const float* __restrict__ W2,
                                                    const float* __restrict__ Wl) {
    extern __shared__ float ts[];             // [na][6][512]
    __shared__ float sred[16][10][2];
    __shared__ int cl[5], cl2[5], s_na, s_na2;
    int bid = blockIdx.x;
    int b = bid >> 7, rem2 = bid & 127;
    int g = rem2 >> 1, half = rem2 & 1;
    int i0 = g * 4, base = half * 500;
    int tid = threadIdx.x, lane = tid & 31, wid = tid >> 5;
    if (tid == 0) {
        int na = 0;
        for (int c = 0; c < 5; ++c) if (g_m1[b * 5 + c]) cl[na++] = c;
        s_na = na;
        int na2 = 0;
        for (int c = 0; c < 5; ++c) if (g_m2[b * 5 + c]) cl2[na2++] = c;
        s_na2 = na2;
    }
    __syncthreads();
    int na = s_na, na2 = s_na2;
    for (int v = tid; v < na * 6 * 128; v += 512) {
        int s = v / 768, rm = v % 768;
        int rr = rm >> 7, jj = rm & 127;
        int col = base + jj * 4;
        float4 val = make_float4(0.f, 0.f, 0.f, 0.f);
        if (col + 3 < H1P)
            val = *(const float4*)&g_h1[((size_t)(b * 5 + cl[s]) * H1 + (i0 + rr)) * H1P + col];
        ((float4*)ts)[v] = val;
    }
    __syncthreads();
    int quad = tid >> 7, t2 = tid & 127;
    int j0 = t2 * 4;
    bool valid = (t2 < 125);
    for (int p = 0; p < (na2 + 1) / 2; ++p) {
        int o0 = cl2[2 * p];
        int o1 = (2 * p + 1 < na2) ? cl2[2 * p + 1] : -1;
        int o1w = (o1 >= 0) ? o1 : o0;
        float acc0[4], acc1[4];
#pragma unroll
        for (int k = 0; k < 4; ++k) { acc0[k] = 0.f; acc1[k] = 0.f; }
        if (valid) {
            for (int s = 0; s < na; ++s) {
                float w0r[9], w1r[9];
#pragma unroll
                for (int k = 0; k < 9; ++k) {
                    w0r[k] = __ldg(&W2[o0 * 45 + cl[s] * 9 + k]);
                    w1r[k] = __ldg(&W2[o1w * 45 + cl[s] * 9 + k]);
                }
#pragma unroll
                for (int rr = 0; rr < 3; ++rr) {       // di == rr: single row
                    const float* ptr = &ts[(s * 6 + quad + rr) * 512 + j0];
                    float4 v4 = *(const float4*)ptr;
                    float2 v2 = *(const float2*)(ptr + 4);
                    float a0 = w0r[rr * 3 + 0], a1 = w0r[rr * 3 + 1], a2 = w0r[rr * 3 + 2];
                    acc0[0] += v4.x * a0 + v4.y * a1 + v4.z * a2;
                    acc0[1] += v4.y * a0 + v4.z * a1 + v4.w * a2;
                    acc0[2] += v4.z * a0 + v4.w * a1 + v2.x * a2;
                    acc0[3] += v4.w * a0 + v2.x * a1 + v2.y * a2;
                    float b0 = w1r[rr * 3 + 0], b1 = w1r[rr * 3 + 1], b2 = w1r[rr * 3 + 2];
                    acc1[0] += v4.x * b0 + v4.y * b1 + v4.z * b2;
                    acc1[1] += v4.y * b0 + v4.z * b1 + v4.w * b2;
                    acc1[2] += v4.z * b0 + v4.w * b1 + v2.x * b2;
                    acc1[3] += v4.w * b0 + v2.x * b1 + v2.y * b2;
                }
            }
        }
        float h00 = fmaxf(acc0[0], 0.f), h01 = fmaxf(acc0[1], 0.f);
        float h02 = fmaxf(acc0[2], 0.f), h03 = fmaxf(acc0[3], 0.f);
        float h10 = fmaxf(acc1[0], 0.f), h11 = fmaxf(acc1[1], 0.f);
        float h12 = fmaxf(acc1[2], 0.f), h13 = fmaxf(acc1[3], 0.f);
#pragma unroll
        for (int t = 0; t < 10; ++t) {
            float v0 = 0.f, v1 = 0.f;
            if (valid) {
                float4 wl = __ldg((const float4*)&Wl[t * 1000 + base + j0]);
                v0 = h00 * wl.x + h01 * wl.y + h02 * wl.z + h03 * wl.w;
                v1 = h10 * wl.x + h11 * wl.y + h12 * wl.z + h13 * wl.w;
            }
            for (int o2 = 16; o2; o2 >>= 1) {
                v0 += __shfl_down_sync(0xffffffffu, v0, o2);
                v1 += __shfl_down_sync(0xffffffffu, v1, o2);
            }
            if (lane == 0) { sred[wid][t][0] = v0; sred[wid][t][1] = v1; }
        }
        __syncthreads();
        if (t2 < 10) {
            int row = i0 + quad;
            float p0 = sred[quad * 4 + 0][t2][0] + sred[quad * 4 + 1][t2][0] +
                       sred[quad * 4 + 2][t2][0] + sred[quad * 4 + 3][t2][0];
            g_pd[(((size_t)(b * 5 + o0) * H2 + row) * 2 + half) * 10 + t2] = p0;
            if (o1 >= 0) {
                float p1 = sred[quad * 4 + 0][t2][1] + sred[quad * 4 + 1][t2][1] +
                           sred[quad * 4 + 2][t2][1] + sred[quad * 4 + 3][t2][1];
                g_pd[(((size_t)(b * 5 + o1) * H2 + row) * 2 + half) * 10 + t2] = p1;
            }
        }
        __syncthreads();
    }
}

// ---------------- combine partials + bias -> out ----------------------------
__global__ __launch_bounds__(256) void k_combine(const float* __restrict__ bl,
                                                 float* __restrict__ out) {
    int bc = blockIdx.x;
    int row = threadIdx.x;
    int m = g_m2[bc];
    size_t obase = ((size_t)bc * H2 + row) * 10;
    size_t pbase = ((size_t)bc * H2 + row) * 20;
#pragma unroll
    for (int t = 0; t < 10; ++t) {
        float v = __ldg(&bl[t]);
        if (m) v += g_pd[pbase + t] + g_pd[pbase + 10 + t];
        out[obase + t] = v;
    }
}

extern "C" void kernel_launch(void* const* d_in, const int* in_sizes, int n_in,
                              void* d_out, int out_size) {
    const float* x  = (const float*)d_in[0];
    const float* W1 = (const float*)d_in[1];
    const float* W2 = (const float*)d_in[2];
    const float* a1 = (const float*)d_in[3];
    const float* b1 = (const float*)d_in[4];
    const float* a2 = (const float*)d_in[5];
    const float* b2 = (const float*)d_in[6];
    const float* Wl = (const float*)d_in[7];
    const float* bl = (const float*)d_in[8];
    float* out = (float*)d_out;
    (void)in_sizes; (void)n_in; (void)out_size;

    cudaFuncSetAttribute(k_conv1, cudaFuncAttributeMaxDynamicSharedMemorySize, C1_SMEM);
    cudaFuncSetAttribute(k_conv2pd, cudaFuncAttributeMaxDynamicSharedMemorySize, C2_SMEM);

    k_filter_hash<<<1, 64>>>(W1, W2, a1, b1, a2, b2);
    k_xrows<<<BATCH * 3 * 4, 256>>>(x);
    k_q1mask<<<BATCH, 32>>>(a1, b1);
    k_conv1<<<BATCH * 65 * 2, 128, C1_SMEM>>>(x, W1);
    k_q2mask<<<BATCH, 160>>>(a2, b2);
    k_conv2pd<<<BATCH * 64 * 2, 512, C2_SMEM>>>(W2, Wl);
    k_combine<<<BATCH * 5, 256>>>(bl, out);
}

// round 9
// speedup vs baseline: 1.0118x; 1.0118x over previous
#include <cuda_runtime.h>
#include <cstdint>

#define BATCH 32
#define H0 260
#define W0 1004
#define H1 258
#define W1W 1002
#define H1P 1004
#define H2 256
#define W2W 1000
#define D1 27
#define D2 45

typedef unsigned long long ull;
__device__ __forceinline__ ull pk(float lo, float hi) {
    ull r; asm("mov.b64 %0, {%1,%2};" : "=l"(r) : "f"(lo), "f"(hi)); return r;
}
__device__ __forceinline__ ull bc2(float v) { return pk(v, v); }
__device__ __forceinline__ void fma2(ull& acc, ull a, ull b) {
    asm("fma.rn.f32x2 %0, %1, %2, %0;" : "+l"(acc) : "l"(a), "l"(b));
}
__device__ __forceinline__ float2 up2(ull v) {
    float2 r; asm("mov.b64 {%0,%1}, %2;" : "=f"(r.x), "=f"(r.y) : "l"(v)); return r;
}

__device__ float g_h1[(size_t)BATCH * 5 * H1 * H1P];
__device__ float g_rsp[(size_t)BATCH * 5 * H1 * 2];
__device__ float g_re[(size_t)BATCH * 5 * H1 * 4];
__device__ float g_xrs[(size_t)BATCH * 3 * H0 * 3];
__device__ float g_pd[(size_t)BATCH * 5 * H2 * 2 * 10];
__device__ int   g_fh1[5];
__device__ int   g_fh2[5];
__device__ int   g_m1[BATCH * 5];
__device__ int   g_m2[BATCH * 5];

// ---------------- filter hashes ---------------------------------------------
__global__ void k_filter_hash(const float* __restrict__ W1, const float* __restrict__ W2,
                              const float* __restrict__ a1, const float* __restrict__ b1,
                              const float* __restrict__ a2, const float* __restrict__ b2) {
    int t = threadIdx.x, lane = t & 31, wrp = t >> 5;
    const float* W = wrp ? W2 : W1;
    const float* a = wrp ? a2 : a1;
    float bb = wrp ? *b2 : *b1;
    int d = wrp ? D2 : D1;
    float ss = 0.f;
    if (lane < 5) for (int k = 0; k < d; ++k) { float v = W[lane * d + k]; ss += v * v; }
    float nrm = sqrtf(ss);
    for (int o = 16; o; o >>= 1) nrm = fmaxf(nrm, __shfl_xor_sync(0xffffffffu, nrm, o));
    float scale = 0.99f / nrm;
    if (lane < 5) {
        float dot = 0.f;
        for (int k = 0; k < d; ++k) dot += (W[lane * d + k] * scale) * a[k];
        float n2 = ss * scale * scale;
        float p2 = n2 * n2, p4 = p2 * p2, p8 = p4 * p4, p16 = p8 * p8;
        dot += n2 * a[d] + p2 * a[d + 1] + p4 * a[d + 2] + p8 * a[d + 3] + p16 * a[d + 4] + bb;
        int h = (int)floorf(dot / 0.1f);
        (wrp ? g_fh2 : g_fh1)[lane] = h & 1;
    }
}

// ---------------- x row restricted sums -------------------------------------
__global__ __launch_bounds__(256) void k_xrows(const float* __restrict__ x) {
    int blk = blockIdx.x, bc = blk >> 2, q = blk & 3;
    int r0 = q * 65;
    int tid = threadIdx.x, lane = tid & 31, wrp = tid >> 5;
    for (int r = r0 + wrp; r < r0 + 65; r += 8) {
        const float* row = x + ((size_t)bc * H0 + r) * W0;
        float s = 0.f;
        for (int col = lane; col < W0; col += 32) s += row[col];
        for (int o = 16; o; o >>= 1) s += __shfl_down_sync(0xffffffffu, s, o);
        if (lane == 0) {
            float e0 = row[0], e1 = row[1], ea = row[W0 - 2], eb = row[W0 - 1];
            float* outp = g_xrs + ((size_t)bc * H0 + r) * 3;
            outp[0] = s - ea - eb;
            outp[1] = s - e0 - eb;
            outp[2] = s - e0 - e1;
        }
    }
}

// ---------------- layer-1 query hash + mask ---------------------------------
__global__ void k_q1mask(const float* __restrict__ a, const float* __restrict__ bp) {
    __shared__ float q[D1];
    int b = blockIdx.x, t = threadIdx.x;
    if (t < D1) {
        int c = t / 9, rem = t % 9, i = rem / 3, j = rem % 3;
        const float* base = g_xrs + ((size_t)(b * 3 + c) * H0) * 3;
        double s = 0.0;
        for (int r = i; r < i + 258; ++r) s += (double)base[r * 3 + j];
        q[t] = (float)(s / (258.0 * 1002.0));
    }
    __syncthreads();
    if (t == 0) {
        float ss = 0.f;
        for (int k = 0; k < D1; ++k) ss += q[k] * q[k];
        float inv = 1.0f / fmaxf(sqrtf(ss), 1e-12f);
        double dot = 0.0;
        for (int k = 0; k < D1; ++k) dot += (double)(q[k] * inv) * (double)a[k];
        dot += 0.5 * ((double)a[D1] + a[D1 + 1] + a[D1 + 2] + a[D1 + 3] + a[D1 + 4]) + (double)*bp;
        int qh = ((int)floor(dot / 0.1)) & 1;
        for (int c = 0; c < 5; ++c) g_m1[b * 5 + c] = (g_fh1[c] == qh) ? 1 : 0;
    }
}

// ---------------- conv1: 6 rows x half-width, 2 ch/pass, f32x2 --------------
#define C1_SMEM (3 * 8 * 512 * 4)

__global__ __launch_bounds__(128, 3) void k_conv1(const float* __restrict__ x,
                                                  const float* __restrict__ W1) {
    extern __shared__ float xs[];            // [3][8][512]
    __shared__ float s_warp[4][6][2];
    __shared__ float sE[6][2][2];
    __shared__ int cl1[5], s_na;
    int bid = blockIdx.x;
    int b = bid / 86, rem2 = bid % 86;
    int g = rem2 >> 1, half = rem2 & 1;
    int i0 = g * 6, base = half * 500;
    int tid = threadIdx.x, lane = tid & 31, wrp = tid >> 5;

    if (tid == 0) {
        int na = 0;
        for (int c = 0; c < 5; ++c) if (g_m1[b * 5 + c]) cl1[na++] = c;
        s_na = na;
    }
    for (int v = tid; v < 3 * 8 * 128; v += 128) {
        int cc = v >> 10, rm = v & 1023;
        int rr = rm >> 7, jj = rm & 127;
        int col = base + jj * 4;
        float4 val = make_float4(0.f, 0.f, 0.f, 0.f);
        if (col + 3 < W0)
            val = *(const float4*)&x[((size_t)(b * 3 + cc) * H0 + (i0 + rr)) * W0 + col];
        ((float4*)xs)[v] = val;
    }
    __syncthreads();
    int na = s_na;
    bool tail = (half == 1 && tid == 125);
    bool valid = (tid < 125) || tail;
    int j0 = tid * 4;

    for (int p = 0; p < (na + 1) / 2; ++p) {
        int o0 = cl1[2 * p];
        int o1 = (2 * p + 1 < na) ? cl1[2 * p + 1] : -1;
        int o1w = (o1 >= 0) ? o1 : o0;
        ull aA[6], aB[6], cA[6], cB[6];   // ch0 pairs (01)(23), ch1 pairs
#pragma unroll
        for (int ri = 0; ri < 6; ++ri) { aA[ri] = 0; aB[ri] = 0; cA[ri] = 0; cB[ri] = 0; }
        if (valid) {
#pragma unroll
            for (int cc = 0; cc < 3; ++cc) {
                ull w0p[9], w1p[9];
#pragma unroll
                for (int k = 0; k < 9; ++k) {
                    w0p[k] = bc2(__ldg(W1 + o0 * 27 + cc * 9 + k));
                    w1p[k] = bc2(__ldg(W1 + o1w * 27 + cc * 9 + k));
                }
#pragma unroll
                for (int rr = 0; rr < 8; ++rr) {
                    const float* ptr = &xs[(cc * 8 + rr) * 512 + j0];
                    float4 v4 = *(const float4*)ptr;
                    float2 v2 = *(const float2*)(ptr + 4);
                    ull P0 = pk(v4.x, v4.y), P1 = pk(v4.y, v4.z), P2 = pk(v4.z, v4.w);
                    ull P3 = pk(v4.w, v2.x), P4 = pk(v2.x, v2.y);
#pragma unroll
                    for (int di = 0; di < 3; ++di) {
                        int ri = rr - di;
                        if (ri >= 0 && ri < 6) {
                            fma2(aA[ri], P0, w0p[di * 3 + 0]);
                            fma2(aA[ri], P1, w0p[di * 3 + 1]);
                            fma2(aA[ri], P2, w0p[di * 3 + 2]);
                            fma2(aB[ri], P2, w0p[di * 3 + 0]);
                            fma2(aB[ri], P3, w0p[di * 3 + 1]);
                            fma2(aB[ri], P4, w0p[di * 3 + 2]);
                            fma2(cA[ri], P0, w1p[di * 3 + 0]);
                            fma2(cA[ri], P1, w1p[di * 3 + 1]);
                            fma2(cA[ri], P2, w1p[di * 3 + 2]);
                            fma2(cB[ri], P2, w1p[di * 3 + 0]);
                            fma2(cB[ri], P3, w1p[di * 3 + 1]);
                            fma2(cB[ri], P4, w1p[di * 3 + 2]);
                        }
                    }
                }
            }
        }
#pragma unroll
        for (int ri = 0; ri < 6; ++ri) {
            float2 fa = up2(aA[ri]), fb = up2(aB[ri]);
            float2 fc = up2(cA[ri]), fd = up2(cB[ri]);
            float p00 = fmaxf(fa.x, 0.f), p01 = fmaxf(fa.y, 0.f);
            float p02 = fmaxf(fb.x, 0.f), p03 = fmaxf(fb.y, 0.f);
            float p10 = fmaxf(fc.x, 0.f), p11 = fmaxf(fc.y, 0.f);
            float p12 = fmaxf(fd.x, 0.f), p13 = fmaxf(fd.y, 0.f);
            float part0 = 0.f, part1 = 0.f;
            if (valid) {
                size_t r0b = ((size_t)(b * 5 + o0) * H1 + (i0 + ri)) * H1P + base + j0;
                if (!tail) {
                    *(float4*)(g_h1 + r0b) = make_float4(p00, p01, p02, p03);
                    part0 = p00 + p01 + p02 + p03;
                } else {
                    g_h1[r0b + 0] = p00; g_h1[r0b + 1] = p01;
                    part0 = p00 + p01;
                }
                if (o1 >= 0) {
                    size_t r1b = ((size_t)(b * 5 + o1) * H1 + (i0 + ri)) * H1P + base + j0;
                    if (!tail) {
                        *(float4*)(g_h1 + r1b) = make_float4(p10, p11, p12, p13);
                        part1 = p10 + p11 + p12 + p13;
                    } else {
                        g_h1[r1b + 0] = p10; g_h1[r1b + 1] = p11;
                        part1 = p10 + p11;
                    }
                }
            }
            if ((half == 0 && tid == 0) || (half == 1 && tid == 125)) {
                sE[ri][0][0] = p00; sE[ri][1][0] = p01;
                sE[ri][0][1] = p10; sE[ri][1][1] = p11;
            }
            for (int o2 = 16; o2; o2 >>= 1) {
                part0 += __shfl_down_sync(0xffffffffu, part0, o2);
                part1 += __shfl_down_sync(0xffffffffu, part1, o2);
            }
            if (lane == 0) { s_warp[wrp][ri][0] = part0; s_warp[wrp][ri][1] = part1; }
        }
        __syncthreads();
        if (tid < 12) {
            int ch = tid / 6, r = tid % 6;
            int oc = ch ? o1 : o0;
            if (oc >= 0) {
                float full = s_warp[0][r][ch] + s_warp[1][r][ch] +
                             s_warp[2][r][ch] + s_warp[3][r][ch];
                size_t row = (size_t)(b * 5 + oc) * H1 + (i0 + r);
                g_rsp[row * 2 + half] = full;
                g_re[row * 4 + half * 2 + 0] = sE[r][0][ch];
                g_re[row * 4 + half * 2 + 1] = sE[r][1][ch];
            }
        }
        __syncthreads();
    }
}

// ---------------- layer-2 query hash + mask ---------------------------------
__global__ void k_q2mask(const float* __restrict__ a, const float* __restrict__ bp) {
    __shared__ float q[D2];
    int b = blockIdx.x, tid = threadIdx.x, lane = tid & 31, c = tid >> 5;
    if (c < 5) {
        if (!g_m1[b * 5 + c]) {
            if (lane < 9) q[c * 9 + lane] = 0.f;
        } else {
            const float* P = g_rsp + (size_t)(b * 5 + c) * H1 * 2;
            const float* E = g_re + (size_t)(b * 5 + c) * H1 * 4;
            double F = 0.0, E0 = 0.0, E1 = 0.0, EA = 0.0, EB = 0.0;
            for (int r = lane; r < H1; r += 32) {
                F  += (double)P[r * 2 + 0] + (double)P[r * 2 + 1];
                E0 += (double)E[r * 4 + 0];
                E1 += (double)E[r * 4 + 1];
                EA += (double)E[r * 4 + 2];
                EB += (double)E[r * 4 + 3];
            }
            for (int o = 16; o; o >>= 1) {
                F  += __shfl_down_sync(0xffffffffu, F, o);
                E0 += __shfl_down_sync(0xffffffffu, E0, o);
                E1 += __shfl_down_sync(0xffffffffu, E1, o);
                EA += __shfl_down_sync(0xffffffffu, EA, o);
                EB += __shfl_down_sync(0xffffffffu, EB, o);
            }
            if (lane == 0) {
                double tot[3] = {F - EA - EB, F - E0 - EB, F - E0 - E1};
                const int rows[4] = {0, 1, 256, 257};
                double rsv[4][3];
                for (int k = 0; k < 4; ++k) {
                    int r = rows[k];
                    double fr = (double)P[r * 2 + 0] + (double)P[r * 2 + 1];
                    double e0 = E[r * 4 + 0], e1 = E[r * 4 + 1];
                    double ea = E[r * 4 + 2], eb = E[r * 4 + 3];
                    rsv[k][0] = fr - ea - eb;
                    rsv[k][1] = fr - e0 - eb;
                    rsv[k][2] = fr - e0 - e1;
                }
                const int exA[3] = {2, 0, 0};
                const int exB[3] = {3, 3, 1};
                for (int i = 0; i < 3; ++i)
                    for (int jo = 0; jo < 3; ++jo)
                        q[c * 9 + i * 3 + jo] =
                            (float)((tot[jo] - rsv[exA[i]][jo] - rsv[exB[i]][jo]) / 256000.0);
            }
        }
    }
    __syncthreads();
    if (tid == 0) {
        float ss = 0.f;
        for (int k = 0; k < D2; ++k) ss += q[k] * q[k];
        float inv = 1.0f / fmaxf(sqrtf(ss), 1e-12f);
        double dot = 0.0;
        for (int k = 0; k < D2; ++k) dot += (double)(q[k] * inv) * (double)a[k];
        dot += 0.5 * ((double)a[D2] + a[D2 + 1] + a[D2 + 2] + a[D2 + 3] + a[D2 + 4]) + (double)*bp;
        int qh = ((int)floor(dot / 0.1)) & 1;
        for (int cc = 0; cc < 5; ++cc) g_m2[b * 5 + cc] = (g_fh2[cc] == qh) ? 1 : 0;
    }
}

// ---------------- conv2 + relu + fused linear, 2 rows/quad, f32x2 ----------
#define C2_SMEM (5 * 10 * 512 * 4)

__global__ __launch_bounds__(512, 1) void k_conv2pd(const float* __restrict__ W2,
                                                    const float* __restrict__ Wl) {
    extern __shared__ float ts[];             // [na][10][512]
    __shared__ float sred[16][10][2];
    __shared__ int cl[5], cl2[5], s_na, s_na2;
    int bid = blockIdx.x;
    int b = bid >> 6, rem2 = bid & 63;
    int g = rem2 >> 1, half = rem2 & 1;
    int i0 = g * 8, base = half * 500;
    int tid = threadIdx.x, lane = tid & 31, wid = tid >> 5;
    if (tid == 0) {
        int na = 0;
        for (int c = 0; c < 5; ++c) if (g_m1[b * 5 + c]) cl[na++] = c;
        s_na = na;
        int na2 = 0;
        for (int c = 0; c < 5; ++c) if (g_m2[b * 5 + c]) cl2[na2++] = c;
        s_na2 = na2;
    }
    __syncthreads();
    int na = s_na, na2 = s_na2;
    for (int v = tid; v < na * 10 * 128; v += 512) {
        int s = v / 1280, rm = v - s * 1280;
        int rr = rm >> 7, jj = rm & 127;
        int col = base + jj * 4;
        float4 val = make_float4(0.f, 0.f, 0.f, 0.f);
        if (col + 3 < H1P)
            val = *(const float4*)&g_h1[((size_t)(b * 5 + cl[s]) * H1 + (i0 + rr)) * H1P + col];
        ((float4*)ts)[v] = val;
    }
    __syncthreads();
    int quad = tid >> 7, t2 = tid & 127;
    int rbase = quad * 2;
    int j0 = t2 * 4;
    bool valid = (t2 < 125);
    for (int p = 0; p < (na2 + 1) / 2; ++p) {
        int o0 = cl2[2 * p];
        int o1 = (2 * p + 1 < na2) ? cl2[2 * p + 1] : -1;
        int o1w = (o1 >= 0) ? o1 : o0;
        ull aA[2], aB[2], cA[2], cB[2];
#pragma unroll
        for (int ri = 0; ri < 2; ++ri) { aA[ri] = 0; aB[ri] = 0; cA[ri] = 0; cB[ri] = 0; }
        if (valid) {
            for (int s = 0; s < na; ++s) {
                ull w0p[9], w1p[9];
#pragma unroll
                for (int k = 0; k < 9; ++k) {
                    w0p[k] = bc2(__ldg(&W2[o0 * 45 + cl[s] * 9 + k]));
                    w1p[k] = bc2(__ldg(&W2[o1w * 45 + cl[s] * 9 + k]));
                }
#pragma unroll
                for (int rr = 0; rr < 4; ++rr) {
                    const float* ptr = &ts[(s * 10 + rbase + rr) * 512 + j0];
                    float4 v4 = *(const float4*)ptr;
                    float2 v2 = *(const float2*)(ptr + 4);
                    ull P0 = pk(v4.x, v4.y), P1 = pk(v4.y, v4.z), P2 = pk(v4.z, v4.w);
                    ull P3 = pk(v4.w, v2.x), P4 = pk(v2.x, v2.y);
#pragma unroll
                    for (int di = 0; di < 3; ++di) {
                        int ri = rr - di;
                        if (ri >= 0 && ri < 2) {
                            fma2(aA[ri], P0, w0p[di * 3 + 0]);
                            fma2(aA[ri], P1, w0p[di * 3 + 1]);
                            fma2(aA[ri], P2, w0p[di * 3 + 2]);
                            fma2(aB[ri], P2, w0p[di * 3 + 0]);
                            fma2(aB[ri], P3, w0p[di * 3 + 1]);
                            fma2(aB[ri], P4, w0p[di * 3 + 2]);
                            fma2(cA[ri], P0, w1p[di * 3 + 0]);
                            fma2(cA[ri], P1, w1p[di * 3 + 1]);
                            fma2(cA[ri], P2, w1p[di * 3 + 2]);
                            fma2(cB[ri], P2, w1p[di * 3 + 0]);
                            fma2(cB[ri], P3, w1p[di * 3 + 1]);
                            fma2(cB[ri], P4, w1p[di * 3 + 2]);
                        }
                    }
                }
            }
        }
#pragma unroll
        for (int ri = 0; ri < 2; ++ri) {
            float2 fa = up2(aA[ri]), fb = up2(aB[ri]);
            float2 fc = up2(cA[ri]), fd = up2(cB[ri]);
            float h00 = fmaxf(fa.x, 0.f), h01 = fmaxf(fa.y, 0.f);
            float h02 = fmaxf(fb.x, 0.f), h03 = fmaxf(fb.y, 0.f);
            float h10 = fmaxf(fc.x, 0.f), h11 = fmaxf(fc.y, 0.f);
            float h12 = fmaxf(fd.x, 0.f), h13 = fmaxf(fd.y, 0.f);
#pragma unroll
            for (int t = 0; t < 10; ++t) {
                float v0 = 0.f, v1 = 0.f;
                if (valid) {
                    float4 wl = __ldg((const float4*)&Wl[t * 1000 + base + j0]);
                    v0 = h00 * wl.x + h01 * wl.y + h02 * wl.z + h03 * wl.w;
                    v1 = h10 * wl.x + h11 * wl.y + h12 * wl.z + h13 * wl.w;
                }
                for (int o2 = 16; o2; o2 >>= 1) {
                    v0 += __shfl_down_sync(0xffffffffu, v0, o2);
                    v1 += __shfl_down_sync(0xffffffffu, v1, o2);
                }
                if (lane == 0) { sred[wid][t][0] = v0; sred[wid][t][1] = v1; }
            }
            __syncthreads();
            if (t2 < 10) {
                int row = i0 + rbase + ri;
                float p0 = sred[quad * 4 + 0][t2][0] + sred[quad * 4 + 1][t2][0] +
                           sred[quad * 4 + 2][t2][0] + sred[quad * 4 + 3][t2][0];
                g_pd[(((size_t)(b * 5 + o0) * H2 + row) * 2 + half) * 10 + t2] = p0;
                if (o1 >= 0) {
                    float p1 = sred[quad * 4 + 0][t2][1] + sred[quad * 4 + 1][t2][1] +
                               sred[quad * 4 + 2][t2][1] + sred[quad * 4 + 3][t2][1];
                    g_pd[(((size_t)(b * 5 + o1) * H2 + row) * 2 + half) * 10 + t2] = p1;
                }
            }
            __syncthreads();
        }
    }
}

// ---------------- combine partials + bias -> out ----------------------------
__global__ __launch_bounds__(256) void k_combine(const float* __restrict__ bl,
                                                 float* __restrict__ out) {
    int bc = blockIdx.x;
    int row = threadIdx.x;
    int m = g_m2[bc];
    size_t obase = ((size_t)bc * H2 + row) * 10;
    size_t pbase = ((size_t)bc * H2 + row) * 20;
#pragma unroll
    for (int t = 0; t < 10; ++t) {
        float v = __ldg(&bl[t]);
        if (m) v += g_pd[pbase + t] + g_pd[pbase + 10 + t];
        out[obase + t] = v;
    }
}

extern "C" void kernel_launch(void* const* d_in, const int* in_sizes, int n_in,
                              void* d_out, int out_size) {
    const float* x  = (const float*)d_in[0];
    const float* W1 = (const float*)d_in[1];
    const float* W2 = (const float*)d_in[2];
    const float* a1 = (const float*)d_in[3];
    const float* b1 = (const float*)d_in[4];
    const float* a2 = (const float*)d_in[5];
    const float* b2 = (const float*)d_in[6];
    const float* Wl = (const float*)d_in[7];
    const float* bl = (const float*)d_in[8];
    float* out = (float*)d_out;
    (void)in_sizes; (void)n_in; (void)out_size;

    cudaFuncSetAttribute(k_conv1, cudaFuncAttributeMaxDynamicSharedMemorySize, C1_SMEM);
    cudaFuncSetAttribute(k_conv2pd, cudaFuncAttributeMaxDynamicSharedMemorySize, C2_SMEM);

    k_filter_hash<<<1, 64>>>(W1, W2, a1, b1, a2, b2);
    k_xrows<<<BATCH * 3 * 4, 256>>>(x);
    k_q1mask<<<BATCH, 32>>>(a1, b1);
    k_conv1<<<BATCH * 43 * 2, 128, C1_SMEM>>>(x, W1);
    k_q2mask<<<BATCH, 160>>>(a2, b2);
    k_conv2pd<<<BATCH * 32 * 2, 512, C2_SMEM>>>(W2, Wl);
    k_combine<<<BATCH * 5, 256>>>(bl, out);
}